// round 9
// baseline (speedup 1.0000x reference)
#include <cuda_runtime.h>

#define C 32
#define H 128
#define W 256
#define MW 128       // w columns per block (w-split x2)
#define YS 36        // y_sh row stride (144B); conflict-free LDS.128 tiling
#define YROWS 194    // rows = staged y cols; rows 192,193 zeroed (boundary mask)
#define ZROW 193
#define GO 66
#define GS 67        // bank stride 3 -> conflict-free
#define GROWS 129    // local w rows 0..127 + pad row 128
#define NT 256

typedef unsigned long long u64;

__device__ __forceinline__ u64 pack2(float lo, float hi) {
    u64 r; asm("mov.b64 %0, {%1, %2};" : "=l"(r) : "f"(lo), "f"(hi)); return r;
}
__device__ __forceinline__ void ffma2(u64& acc, u64 a, u64 b) {
    asm("fma.rn.f32x2 %0, %1, %2, %0;" : "+l"(acc) : "l"(a), "l"(b));
}
__device__ __forceinline__ u64 add2(u64 a, u64 b) {
    u64 r; asm("add.rn.f32x2 %0, %1, %2;" : "=l"(r) : "l"(a), "l"(b)); return r;
}
__device__ __forceinline__ float hadd2(u64 v) {
    float lo, hi; asm("mov.b64 {%0, %1}, %2;" : "=f"(lo), "=f"(hi) : "l"(v)); return lo + hi;
}

__global__ __launch_bounds__(NT, 3)
void cost_volume_kernel(const float* __restrict__ x, const float* __restrict__ y,
                        const float* __restrict__ disp, float* __restrict__ out,
                        int D) {
    extern __shared__ float sm[];
    float* y_sh = sm;                  // YROWS * YS ; row r = y column (yoff + r)
    float* G_sh = sm + YROWS * YS;     // GROWS * GS banded Gram (local w rows)

    const int blk = blockIdx.x;
    const int s = blk & 1;             // w-half: 0 -> cols [0,128), 1 -> [128,256)
    const int bh = blk >> 1;
    const int b = bh / H;
    const int h = bh - b * H;
    const int w0 = s << 7;             // 0 or 128
    const int yoff = s << 6;           // staged y col of row 0: 0 or 64
    const int nvalid = s ? 192 : 129;  // staged rows (y cols yoff .. yoff+nvalid-1)
    const int yadd = s << 6;           // local r = w_local + o0 - 64 + yadd

    const int tid = threadIdx.x;
    const size_t HW = (size_t)H * W;
    const float* ybase = y + ((size_t)b * C * H + h) * W;
    const float* xbase = x + ((size_t)b * C * H + h) * W;

    // ---- Phase 1: stage y cols [yoff, yoff+nvalid) transposed; rows 192/193
    // zeroed (implement the reference's zero-padding mask at both edges).
    if (tid < YROWS) {
        float* dst = y_sh + tid * YS;
        if (tid < nvalid) {
            const float* src = ybase + (yoff + tid);
            #pragma unroll
            for (int c = 0; c < C; c += 4) {
                float v0 = src[(size_t)(c + 0) * HW];
                float v1 = src[(size_t)(c + 1) * HW];
                float v2 = src[(size_t)(c + 2) * HW];
                float v3 = src[(size_t)(c + 3) * HW];
                *(float4*)(dst + c) = make_float4(v0, v1, v2, v3);
            }
        } else if (tid >= 192) {
            #pragma unroll
            for (int c = 0; c < C; c += 4)
                *(float4*)(dst + c) = make_float4(0.f, 0.f, 0.f, 0.f);
        }
    }

    // Thread layout: 8 warps x 16 cols; lane halves split channels.
    const int lane = tid & 31;
    const int half = lane >> 4;          // c in [16*half, 16*half+16)
    const int wl = ((tid >> 5) << 4) | (lane & 15);   // local col 0..127
    const int wg = w0 + wl;              // global col
    const int cb = half * 16;
    const bool has_b = (wg + 1 < W);

    // x columns wg, wg+1 (this half's 16 channels), packed for FFMA2.
    u64 xa[8], xb[8];
    #pragma unroll
    for (int k = 0; k < 8; k++) {
        float a0 = xbase[(size_t)(cb + 2 * k) * HW + wg];
        float a1 = xbase[(size_t)(cb + 2 * k + 1) * HW + wg];
        xa[k] = pack2(a0, a1);
        float b0 = has_b ? xbase[(size_t)(cb + 2 * k) * HW + wg + 1] : 0.f;
        float b1 = has_b ? xbase[(size_t)(cb + 2 * k + 1) * HW + wg + 1] : 0.f;
        xb[k] = pack2(b0, b1);
    }
    __syncthreads();

    // ---- Phase 2: banded Gram  G[wg][o] = sum_c x[c][wg] * y[c][wg+o-64]
    // Anti-diagonal pairing: (wg, o0) and (wg+1, o0-1) share y column wg+o0-64
    // (local row wl + o0 - 64 + yadd; negative -> zero row; row 192 is the
    // upper-edge zero row for block B).
    #pragma unroll 1
    for (int o0 = 1; o0 <= 65; o0 += 2) {
        int r = wl + o0 - 64 + yadd;
        if (r < 0) r = ZROW;
        const ulonglong2* yp = (const ulonglong2*)(y_sh + r * YS + cb);
        ulonglong2 q0 = yp[0], q1 = yp[1], q2 = yp[2], q3 = yp[3];
        u64 a0 = 0, a1 = 0, b0 = 0, b1 = 0;
        ffma2(a0, xa[0], q0.x);  ffma2(b0, xb[0], q0.x);
        ffma2(a1, xa[1], q0.y);  ffma2(b1, xb[1], q0.y);
        ffma2(a0, xa[2], q1.x);  ffma2(b0, xb[2], q1.x);
        ffma2(a1, xa[3], q1.y);  ffma2(b1, xb[3], q1.y);
        ffma2(a0, xa[4], q2.x);  ffma2(b0, xb[4], q2.x);
        ffma2(a1, xa[5], q2.y);  ffma2(b1, xb[5], q2.y);
        ffma2(a0, xa[6], q3.x);  ffma2(b0, xb[6], q3.x);
        ffma2(a1, xa[7], q3.y);  ffma2(b1, xb[7], q3.y);
        float av = hadd2(add2(a0, a1));
        float bv = hadd2(add2(b0, b1));
        av += __shfl_xor_sync(0xFFFFFFFFu, av, 16);
        bv += __shfl_xor_sync(0xFFFFFFFFu, bv, 16);
        if (half == 0) G_sh[wl * GS + o0] = av;                 // (wg, odd o)
        else           G_sh[(wl + 1) * GS + (o0 - 1)] = bv;     // (wg+1, even o); wl=127 -> pad row
    }
    // Cleanup: (local w=0, even o). Block A: zero except o=64 (y col 0).
    // Block B: real dots at y rows r = o (cols 64+o).
    if (tid < 33) {
        int o = 2 * tid;
        int r = o - 64 + yadd;
        float ssum = 0.f;
        if (r >= 0) {
            #pragma unroll
            for (int c = 0; c < C; c++)
                ssum = fmaf(xbase[(size_t)c * HW + w0], y_sh[r * YS + c], ssum);
        }
        G_sh[o] = ssum;
    }

    // ---- Phase 3 prologue: disp loads issued before the barrier.
    const float* dbase = disp + ((size_t)b * D * H + h) * W + w0;
    float* obase = out + ((size_t)b * D * H + h) * W + w0;

    if (D == 48) {
        float4 dv[6];
        #pragma unroll
        for (int k = 0; k < 6; k++) {
            int i = tid + k * NT;          // i in [0, 1536)
            int d = i >> 5;                // 32 float4 per d (128 cols)
            int w4 = (i & 31) << 2;
            dv[k] = *(const float4*)(dbase + (size_t)d * HW + w4);
        }
        __syncthreads();
        #pragma unroll
        for (int k = 0; k < 6; k++) {
            int i = tid + k * NT;
            int d = i >> 5;
            int w4 = (i & 31) << 2;
            float4 res;
            #pragma unroll
            for (int j = 0; j < 4; j++) {
                int wwl = w4 + j;
                int wwg = w0 + wwl;
                float px = (float)wwg - (&dv[k].x)[j];
                float x0f = floorf(px);
                float fx = px - x0f;
                int o = (int)x0f - wwg + 64;
                float g0 = ((unsigned)o < GO) ? G_sh[wwl * GS + o] : 0.f;
                float g1 = ((unsigned)(o + 1) < GO) ? G_sh[wwl * GS + o + 1] : 0.f;
                (&res.x)[j] = (g0 + (g1 - g0) * fx) * (1.0f / C);
            }
            *(float4*)(obase + (size_t)d * HW + w4) = res;
        }
    } else {
        __syncthreads();
        const int total4 = D * (MW / 4);
        for (int i = tid; i < total4; i += NT) {
            int d = i >> 5;
            int w4 = (i & 31) << 2;
            float4 dvv = *(const float4*)(dbase + (size_t)d * HW + w4);
            float4 res;
            #pragma unroll
            for (int j = 0; j < 4; j++) {
                int wwl = w4 + j;
                int wwg = w0 + wwl;
                float px = (float)wwg - (&dvv.x)[j];
                float x0f = floorf(px);
                float fx = px - x0f;
                int o = (int)x0f - wwg + 64;
                float g0 = ((unsigned)o < GO) ? G_sh[wwl * GS + o] : 0.f;
                float g1 = ((unsigned)(o + 1) < GO) ? G_sh[wwl * GS + o + 1] : 0.f;
                (&res.x)[j] = (g0 + (g1 - g0) * fx) * (1.0f / C);
            }
            *(float4*)(obase + (size_t)d * HW + w4) = res;
        }
    }
}

extern "C" void kernel_launch(void* const* d_in, const int* in_sizes, int n_in,
                              void* d_out, int out_size) {
    const float* x = (const float*)d_in[0];
    const float* y = (const float*)d_in[1];
    const float* disp = (const float*)d_in[2];
    int B = in_sizes[0] / (C * H * W);
    int D = in_sizes[2] / (B * H * W);
    int smem = (YROWS * YS + GROWS * GS) * (int)sizeof(float);
    cudaFuncSetAttribute(cost_volume_kernel,
                         cudaFuncAttributeMaxDynamicSharedMemorySize, smem);
    cost_volume_kernel<<<B * H * 2, NT, smem>>>(x, y, disp, (float*)d_out, D);
}

// round 10
// speedup vs baseline: 1.1084x; 1.1084x over previous
#include <cuda_runtime.h>

#define C 32
#define H 128
#define W 256
#define YS 36        // y_sh row stride (144B): lane bank stride 4 -> conflict-free LDS.128
#define YROWS 257    // rows 0..255 = y columns; row 256 = zero row (both boundaries)
#define GO 66
#define GS 67
#define GROWS 257    // rows 0..255 real; row 256 pads the w=255 b-store
#define NT 256

typedef unsigned long long u64;

__device__ __forceinline__ u64 pack2(float lo, float hi) {
    u64 r; asm("mov.b64 %0, {%1, %2};" : "=l"(r) : "f"(lo), "f"(hi)); return r;
}
__device__ __forceinline__ void ffma2(u64& acc, u64 a, u64 b) {
    asm("fma.rn.f32x2 %0, %1, %2, %0;" : "+l"(acc) : "l"(a), "l"(b));
}
__device__ __forceinline__ u64 add2(u64 a, u64 b) {
    u64 r; asm("add.rn.f32x2 %0, %1, %2;" : "=l"(r) : "l"(a), "l"(b)); return r;
}
__device__ __forceinline__ float hadd2(u64 v) {
    float lo, hi; asm("mov.b64 {%0, %1}, %2;" : "=f"(lo), "=f"(hi) : "l"(v)); return lo + hi;
}

__global__ __launch_bounds__(NT, 2)
void cost_volume_kernel(const float* __restrict__ x, const float* __restrict__ y,
                        const float* __restrict__ disp, float* __restrict__ out,
                        int D) {
    extern __shared__ float sm[];
    float* y_sh = sm;                  // YROWS * YS ([col][c]; row 256 = zeros)
    float* G_sh = sm + YROWS * YS;     // GROWS * GS banded Gram

    const int bh = blockIdx.x;
    const int b = bh / H;
    const int h = bh - b * H;
    const int tid = threadIdx.x;
    const size_t HW = (size_t)H * W;
    const float* ybase = y + ((size_t)b * C * H + h) * W;
    const float* xbase = x + ((size_t)b * C * H + h) * W;

    // ---- Phase 1: stage y row transposed (row r = y column r). Row 256 is
    // the zero row implementing the reference's zero-padding mask.
    {
        const float* src = ybase + tid;
        float* dst = y_sh + tid * YS;
        #pragma unroll
        for (int c = 0; c < C; c += 4) {
            float v0 = src[(size_t)(c + 0) * HW];
            float v1 = src[(size_t)(c + 1) * HW];
            float v2 = src[(size_t)(c + 2) * HW];
            float v3 = src[(size_t)(c + 3) * HW];
            *(float4*)(dst + c) = make_float4(v0, v1, v2, v3);
        }
    }
    if (tid < YS) y_sh[256 * YS + tid] = 0.0f;

    // x columns w and w+1, all 32 channels, packed for FFMA2.
    const int w = tid;                // blockDim.x == W
    const bool has_b = (w + 1 < W);
    u64 xa[16], xb[16];
    #pragma unroll
    for (int k = 0; k < 16; k++) {
        float a0 = xbase[(size_t)(2 * k) * HW + w];
        float a1 = xbase[(size_t)(2 * k + 1) * HW + w];
        xa[k] = pack2(a0, a1);
        float b0 = has_b ? xbase[(size_t)(2 * k) * HW + w + 1] : 0.f;
        float b1 = has_b ? xbase[(size_t)(2 * k + 1) * HW + w + 1] : 0.f;
        xb[k] = pack2(b0, b1);
    }
    __syncthreads();

    // ---- Phase 2: banded Gram  G[w][o] = sum_c x[c][w] * y[c][w+o-64]
    // Anti-diagonal pairing: (w, o0) and (w+1, o0-1) share y column w+o0-64.
    // r < 0 clamps to the zero row; r == 256 (w=255,o0=65) is already zero.
    // unroll 2: iterations are independent -> ptxas software-pipelines the
    // LDS.128s of iter k+1 above the FFMA2 chain of iter k.
    float* ga = G_sh + w * GS;
    float* gb = G_sh + (w + 1) * GS;
    #pragma unroll 2
    for (int o0 = 1; o0 <= 65; o0 += 2) {
        int r = w + o0 - 64;
        if (r < 0) r = 256;
        const ulonglong2* yp = (const ulonglong2*)(y_sh + r * YS);
        ulonglong2 q0 = yp[0], q1 = yp[1], q2 = yp[2], q3 = yp[3];
        ulonglong2 q4 = yp[4], q5 = yp[5], q6 = yp[6], q7 = yp[7];
        u64 a0 = 0, a1 = 0, a2 = 0, a3 = 0;
        u64 b0 = 0, b1 = 0, b2 = 0, b3 = 0;
        ffma2(a0, xa[0],  q0.x);  ffma2(b0, xb[0],  q0.x);
        ffma2(a1, xa[1],  q0.y);  ffma2(b1, xb[1],  q0.y);
        ffma2(a2, xa[2],  q1.x);  ffma2(b2, xb[2],  q1.x);
        ffma2(a3, xa[3],  q1.y);  ffma2(b3, xb[3],  q1.y);
        ffma2(a0, xa[4],  q2.x);  ffma2(b0, xb[4],  q2.x);
        ffma2(a1, xa[5],  q2.y);  ffma2(b1, xb[5],  q2.y);
        ffma2(a2, xa[6],  q3.x);  ffma2(b2, xb[6],  q3.x);
        ffma2(a3, xa[7],  q3.y);  ffma2(b3, xb[7],  q3.y);
        ffma2(a0, xa[8],  q4.x);  ffma2(b0, xb[8],  q4.x);
        ffma2(a1, xa[9],  q4.y);  ffma2(b1, xb[9],  q4.y);
        ffma2(a2, xa[10], q5.x);  ffma2(b2, xb[10], q5.x);
        ffma2(a3, xa[11], q5.y);  ffma2(b3, xb[11], q5.y);
        ffma2(a0, xa[12], q6.x);  ffma2(b0, xb[12], q6.x);
        ffma2(a1, xa[13], q6.y);  ffma2(b1, xb[13], q6.y);
        ffma2(a2, xa[14], q7.x);  ffma2(b2, xb[14], q7.x);
        ffma2(a3, xa[15], q7.y);  ffma2(b3, xb[15], q7.y);
        ga[o0]     = hadd2(add2(add2(a0, a1), add2(a2, a3)));
        gb[o0 - 1] = hadd2(add2(add2(b0, b1), add2(b2, b3)));
    }
    // Cleanup: entries (w=0, even o): zero except the single real dot at o=64.
    if (tid < 33) {
        int o = 2 * tid;
        float s = 0.f;
        if (o == 64) {
            #pragma unroll
            for (int c = 0; c < C; c++)
                s = fmaf(xbase[(size_t)c * HW], y_sh[0 * YS + c], s);
        }
        G_sh[o] = s;
    }

    // ---- Phase 3 prologue: disp loads before the barrier (latency hidden
    // under other warps' phase-2 tail).
    const float* dbase = disp + ((size_t)b * D * H + h) * W;
    float* obase = out + ((size_t)b * D * H + h) * W;

    // disp in [0,64) => o = floor(w-disp)-w+64 in [0,64], o+1 in [1,65]:
    // always inside the band and inside the GS=67 row -> no guards needed.
    if (D == 48) {
        float4 dv[12];
        #pragma unroll
        for (int k = 0; k < 12; k++) {
            int i = tid + k * NT;
            int d = i >> 6;               // 64 float4 per d
            int w4 = (i & 63) << 2;
            dv[k] = *(const float4*)(dbase + (size_t)d * HW + w4);
        }
        __syncthreads();
        #pragma unroll
        for (int k = 0; k < 12; k++) {
            int i = tid + k * NT;
            int d = i >> 6;
            int w4 = (i & 63) << 2;
            float4 res;
            #pragma unroll
            for (int j = 0; j < 4; j++) {
                int ww = w4 + j;
                float px = (float)ww - (&dv[k].x)[j];
                float x0f = floorf(px);
                float fx = px - x0f;
                int o = (int)x0f - ww + 64;
                float g0 = G_sh[ww * GS + o];
                float g1 = G_sh[ww * GS + o + 1];
                (&res.x)[j] = (g0 + (g1 - g0) * fx) * (1.0f / C);
            }
            *(float4*)(obase + (size_t)d * HW + w4) = res;
        }
    } else {
        __syncthreads();
        const int total4 = D * (W / 4);
        #pragma unroll 4
        for (int i = tid; i < total4; i += NT) {
            int d = i >> 6;
            int w4 = (i & 63) << 2;
            float4 dvv = *(const float4*)(dbase + (size_t)d * HW + w4);
            float4 res;
            #pragma unroll
            for (int j = 0; j < 4; j++) {
                int ww = w4 + j;
                float px = (float)ww - (&dvv.x)[j];
                float x0f = floorf(px);
                float fx = px - x0f;
                int o = (int)x0f - ww + 64;
                float g0 = ((unsigned)o < GO) ? G_sh[ww * GS + o] : 0.f;
                float g1 = ((unsigned)(o + 1) < GO) ? G_sh[ww * GS + o + 1] : 0.f;
                (&res.x)[j] = (g0 + (g1 - g0) * fx) * (1.0f / C);
            }
            *(float4*)(obase + (size_t)d * HW + w4) = res;
        }
    }
}

extern "C" void kernel_launch(void* const* d_in, const int* in_sizes, int n_in,
                              void* d_out, int out_size) {
    const float* x = (const float*)d_in[0];
    const float* y = (const float*)d_in[1];
    const float* disp = (const float*)d_in[2];
    int B = in_sizes[0] / (C * H * W);
    int D = in_sizes[2] / (B * H * W);
    int smem = (YROWS * YS + GROWS * GS) * (int)sizeof(float);
    cudaFuncSetAttribute(cost_volume_kernel,
                         cudaFuncAttributeMaxDynamicSharedMemorySize, smem);
    cost_volume_kernel<<<B * H, NT, smem>>>(x, y, disp, (float*)d_out, D);
}